// round 5
// baseline (speedup 1.0000x reference)
#include <cuda_runtime.h>
#include <stdint.h>
#include <math.h>

#define NQ   12
#define NL   6
#define NC   64
#define TPB  256
#define ST   17                   // float stride per thread-row per plane
#define PLANE (TPB * ST)          // 4352 floats per plane
#define BUFSZ (2 * PLANE)         // R plane + I plane per buffer

typedef unsigned long long u64;

// Amp bits: C = i[11:8] (wires 0-3), B = i[7:4] (wires 4-7), A = i[3:0] (wires 8-11).
// M0: tid=(C<<4)|B, k=A.  M1 (revised): row = C[3:1]<<5 | A0<<4 | C0<<3 | A[3:1], k=B.
// M2: tid=(A<<4)|B, k=C.  Packed regs: lane0 = k even, lane1 = k odd (u64 f32x2 carrier).

extern __shared__ float dynsm[];   // [2][BUFSZ]

__device__ __forceinline__ u64 bc2(float c){ u64 r; asm("mov.b64 %0, {%1, %1};" : "=l"(r) : "f"(c)); return r; }
__device__ __forceinline__ u64 pk2(float lo, float hi){ u64 r; asm("mov.b64 %0, {%1, %2};" : "=l"(r) : "f"(lo), "f"(hi)); return r; }
__device__ __forceinline__ float lo32(u64 v){ float f; asm("{ .reg .f32 h; mov.b64 {%0, h}, %1; }" : "=f"(f) : "l"(v)); return f; }
__device__ __forceinline__ float hi32(u64 v){ float f; asm("{ .reg .f32 l; mov.b64 {l, %0}, %1; }" : "=f"(f) : "l"(v)); return f; }
__device__ __forceinline__ u64 mul2(u64 a, u64 b){ u64 r; asm("mul.rn.f32x2 %0, %1, %2;" : "=l"(r) : "l"(a), "l"(b)); return r; }
__device__ __forceinline__ u64 fma2(u64 a, u64 b, u64 c){ u64 r; asm("fma.rn.f32x2 %0, %1, %2, %3;" : "=l"(r) : "l"(a), "l"(b), "l"(c)); return r; }
__device__ __forceinline__ u64 add2(u64 a, u64 b){ u64 r; asm("add.rn.f32x2 %0, %1, %2;" : "=l"(r) : "l"(a), "l"(b)); return r; }
__device__ __forceinline__ u64 sub2(u64 a, u64 b){ u64 r; asm("sub.rn.f32x2 %0, %1, %2;" : "=l"(r) : "l"(a), "l"(b)); return r; }
// componentwise C2*T + S2*U  (2 SASS ops, no movs)
__device__ __forceinline__ u64 rxh(u64 C2, u64 S2, u64 T, u64 U){ return fma2(C2, T, mul2(S2, U)); }

// RX on 4 register-local wires w0..w0+3 (k-bit masks 8,4,2,1)
__device__ __forceinline__ void rx_group(u64* R, u64* I, const float* cl, const float* sl, int w0)
{
#pragma unroll
    for (int n = 0; n < 3; ++n) {            // masks 8,4,2 -> packed masks 4,2,1
        const int mp = 4 >> n;
        const float c = cl[w0 + n], s = sl[w0 + n];
        const u64 C2 = bc2(c), S2 = bc2(s), N2 = bc2(-s);
#pragma unroll
        for (int p0 = 0; p0 < 8; ++p0) {
            if (p0 & mp) continue;
            const int p1 = p0 | mp;
            const u64 r0 = R[p0], i0 = I[p0], r1 = R[p1], i1 = I[p1];
            R[p0] = rxh(C2, S2, r0, i1);
            I[p0] = rxh(C2, N2, i0, r1);
            R[p1] = rxh(C2, S2, r1, i0);
            I[p1] = rxh(C2, N2, i1, r0);
        }
    }
    {   // mask 1: partner inside the packed reg -> scalar lanes
        const float c = cl[w0 + 3], s = sl[w0 + 3];
#pragma unroll
        for (int p = 0; p < 8; ++p) {
            const float rx = lo32(R[p]), ry = hi32(R[p]);
            const float ix = lo32(I[p]), iy = hi32(I[p]);
            R[p] = pk2(fmaf(c, rx,  s * iy), fmaf(c, ry,  s * ix));
            I[p] = pk2(fmaf(c, ix, -s * ry), fmaf(c, iy, -s * rx));
        }
    }
}

#define ROWC(C) ((((C) >> 1) << 5) | (((C) & 1) << 3))

__global__ __launch_bounds__(TPB, 2)
void qnn_kernel(const float* __restrict__ x,
                const float* __restrict__ qw,
                const float* __restrict__ W,
                const float* __restrict__ bias,
                float* __restrict__ out)
{
    __shared__ float cx[NQ], sx[NQ];
    __shared__ float cq[NL * NQ], sq[NL * NQ];
    __shared__ float red[8][NQ];
    __shared__ float zf[NQ];

    float* const buf0 = dynsm;
    float* const buf1 = dynsm + BUFSZ;

    const int tid  = threadIdx.x;
    const int bsmp = blockIdx.x;
    const int lane = tid & 31;
    const int warp = tid >> 5;

    if (tid < NQ) {
        float s, c;
        sincosf(0.5f * x[bsmp * NQ + tid], &s, &c);
        cx[tid] = c; sx[tid] = s;
    }
    if (tid >= 32 && tid < 32 + NL * NQ) {
        const int idx = tid - 32;
        float s, c;
        sincosf(0.5f * qw[idx], &s, &c);
        cq[idx] = c; sq[idx] = s;
    }
    __syncthreads();

    // ---- init (M0): fused AngleEmbedding product state, planar packed ----
    u64 R[8], I[8];
    uint32_t off3p[8];                    // packed Q3 gather offsets (2x u16)
    const int base = tid << 4;

#pragma unroll
    for (int k = 0; k < 16; ++k) {
        const int i = base | k;
        float mag = 1.0f;
#pragma unroll
        for (int w = 0; w < NQ; ++w)
            mag *= ((i >> (11 - w)) & 1) ? sx[w] : cx[w];
        const int pc = __popc(i) & 3;     // amp = mag * (-i)^popcount
        float re = 0.f, im = 0.f;
        if      (pc == 0) re =  mag;
        else if (pc == 1) im = -mag;
        else if (pc == 2) re = -mag;
        else              im =  mag;

        if (k & 1) { R[k >> 1] = pk2(lo32(R[k >> 1]), re); I[k >> 1] = pk2(lo32(I[k >> 1]), im); }
        else       { R[k >> 1] = pk2(re, 0.f);             I[k >> 1] = pk2(im, 0.f); }

        // sigma(i): CNOT-ring gather source, addressed in M2 layout
        int j = i;
#pragma unroll
        for (int w = NQ - 1; w >= 0; --w) {
            const int t  = (w + 1) % NQ;
            const int bc = (j >> (11 - w)) & 1;
            j ^= bc << (11 - t);
        }
        const uint32_t off = (uint32_t)(((((j & 15) << 4) | ((j >> 4) & 15)) * ST) + (j >> 8));
        if (k & 1) off3p[k >> 1] |= off << 16;
        else       off3p[k >> 1]  = off;
    }

    // per-round address bases
    const int st = tid * ST;                                            // own-row store base
    const int A0 = (tid >> 4) & 1, C0 = (tid >> 3) & 1;                 // Q1 dest decode (M1)
    const int Aq1 = ((tid & 7) << 1) | A0;
    const int Cq1 = ((tid >> 5) << 1) | C0;
    const int base1 = Cq1 * (16 * ST) + Aq1;
    const int Aq2 = tid >> 4;                                           // Q2 dest decode (M2)
    const int base2 = ((((Aq2 & 1) << 4) | (Aq2 >> 1)) * ST) + (tid & 15);

    // ---- 6 entangler layers ----
#pragma unroll 1
    for (int l = 0; l < NL; ++l) {
        const float* cl = &cq[l * NQ];
        const float* sl = &sq[l * NQ];
        float* const bA = (l & 1) ? buf1 : buf0;   // rounds Q1, Q3
        float* const bB = (l & 1) ? buf0 : buf1;   // round  Q2
        float* const bAi = bA + PLANE;
        float* const bBi = bB + PLANE;

        rx_group(R, I, cl, sl, 8);                 // wires 8..11 (M0, k=A)

        // Q1: M0 -> M1(revised)
#pragma unroll
        for (int p = 0; p < 8; ++p) {
            bA[st + 2*p] = lo32(R[p]); bA[st + 2*p + 1] = hi32(R[p]);
            bAi[st + 2*p] = lo32(I[p]); bAi[st + 2*p + 1] = hi32(I[p]);
        }
        __syncthreads();
#pragma unroll
        for (int B = 0; B < 16; B += 2) {
            R[B >> 1] = pk2(bA[base1 + B * ST],  bA[base1 + (B + 1) * ST]);
            I[B >> 1] = pk2(bAi[base1 + B * ST], bAi[base1 + (B + 1) * ST]);
        }

        rx_group(R, I, cl, sl, 4);                 // wires 4..7 (M1, k=B)

        // Q2: M1 -> M2
#pragma unroll
        for (int p = 0; p < 8; ++p) {
            bB[st + 2*p] = lo32(R[p]); bB[st + 2*p + 1] = hi32(R[p]);
            bBi[st + 2*p] = lo32(I[p]); bBi[st + 2*p + 1] = hi32(I[p]);
        }
        __syncthreads();
#pragma unroll
        for (int C = 0; C < 16; C += 2) {
            R[C >> 1] = pk2(bB[base2 + ROWC(C) * ST],  bB[base2 + ROWC(C + 1) * ST]);
            I[C >> 1] = pk2(bBi[base2 + ROWC(C) * ST], bBi[base2 + ROWC(C + 1) * ST]);
        }

        rx_group(R, I, cl, sl, 0);                 // wires 0..3 (M2, k=C)

        // Q3: fused CNOT-ring permutation, M2 -> M0
#pragma unroll
        for (int p = 0; p < 8; ++p) {
            bA[st + 2*p] = lo32(R[p]); bA[st + 2*p + 1] = hi32(R[p]);
            bAi[st + 2*p] = lo32(I[p]); bAi[st + 2*p + 1] = hi32(I[p]);
        }
        __syncthreads();
#pragma unroll
        for (int k = 0; k < 16; k += 2) {
            const int o0 = off3p[k >> 1] & 0xFFFF;
            const int o1 = off3p[k >> 1] >> 16;
            R[k >> 1] = pk2(bA[o0],  bA[o1]);
            I[k >> 1] = pk2(bAi[o0], bAi[o1]);
        }
    }

    // ---- <Z_w> readout (M0, planar packed) ----
    u64 pt2 = 0ull, z8 = 0ull, z9 = 0ull, z10 = 0ull;
    float z11 = 0.f;
#pragma unroll
    for (int p = 0; p < 8; ++p) {
        const u64 P = fma2(R[p], R[p], mul2(I[p], I[p]));
        pt2 = add2(pt2, P);
        z8  = (p & 4) ? sub2(z8,  P) : add2(z8,  P);
        z9  = (p & 2) ? sub2(z9,  P) : add2(z9,  P);
        z10 = (p & 1) ? sub2(z10, P) : add2(z10, P);
        z11 += lo32(P) - hi32(P);
    }
    const float ptot = lo32(pt2) + hi32(pt2);

    float z12[NQ];
#pragma unroll
    for (int w = 0; w < 8; ++w)                  // wires 0..7: sign fixed per thread
        z12[w] = ((tid >> (7 - w)) & 1) ? -ptot : ptot;
    z12[8]  = lo32(z8)  + hi32(z8);
    z12[9]  = lo32(z9)  + hi32(z9);
    z12[10] = lo32(z10) + hi32(z10);
    z12[11] = z11;

#pragma unroll
    for (int w = 0; w < NQ; ++w) {
#pragma unroll
        for (int o = 16; o > 0; o >>= 1)
            z12[w] += __shfl_xor_sync(0xffffffffu, z12[w], o);
    }
    if (lane == 0) {
#pragma unroll
        for (int w = 0; w < NQ; ++w) red[warp][w] = z12[w];
    }
    __syncthreads();
    if (tid < NQ) {
        float acc = 0.f;
#pragma unroll
        for (int ww = 0; ww < 8; ++ww) acc += red[ww][tid];
        zf[tid] = acc;
    }
    __syncthreads();

    // ---- classifier head ----
    if (tid < NC) {
        float acc = bias[tid];
#pragma unroll
        for (int w = 0; w < NQ; ++w)
            acc = fmaf(zf[w], W[tid * NQ + w], acc);
        out[bsmp * NC + tid] = acc;
    }
}

extern "C" void kernel_launch(void* const* d_in, const int* in_sizes, int n_in,
                              void* d_out, int out_size)
{
    const float* x  = (const float*)d_in[0];   // (512, 12)
    const float* qw = (const float*)d_in[1];   // (6, 12)
    const float* W  = (const float*)d_in[2];   // (64, 12)
    const float* bs = (const float*)d_in[3];   // (64,)
    float* out = (float*)d_out;                // (512, 64)

    const int smem = 2 * BUFSZ * (int)sizeof(float);   // 69632 B
    cudaFuncSetAttribute(qnn_kernel, cudaFuncAttributeMaxDynamicSharedMemorySize, smem);
    qnn_kernel<<<512, TPB, smem>>>(x, qw, W, bs, out);
}

// round 6
// speedup vs baseline: 1.0576x; 1.0576x over previous
#include <cuda_runtime.h>
#include <stdint.h>
#include <math.h>

#define NQ   12
#define NL   6
#define NC   64
#define TPB  128
#define ST   33                    // float stride per thread-row per plane (odd -> conflict-free)
#define PLANE (TPB * ST)           // 4224 floats per plane
#define SMEMF (2 * PLANE)          // R plane + I plane (single buffer)

typedef unsigned long long u64;

// Amp bits (i[11:0], wire w = bit 11-w):
// M0: T = i[11:5], k = i[4:0]; packed p = i[4:1] (wires 7-10), pair-lane = i[0] (wire 11)
// M1: T = (i[11:10]<<5)|i[4:0], k' = i[9:5]; p' = i[9:6] (wires 2-5), lane = i[5] (wire 6)
// M2: T = (i[9:8]<<5)|i[4:0], k'' = (i[11:10]<<3)|i[7:5]; p'' bits 3,2 = wires 0,1

extern __shared__ float dynsm[];   // [2][PLANE]

__device__ __forceinline__ u64 bc2(float c){ u64 r; asm("mov.b64 %0, {%1, %1};" : "=l"(r) : "f"(c)); return r; }
__device__ __forceinline__ u64 pk2(float lo, float hi){ u64 r; asm("mov.b64 %0, {%1, %2};" : "=l"(r) : "f"(lo), "f"(hi)); return r; }
__device__ __forceinline__ float lo32(u64 v){ float f; asm("{ .reg .f32 h; mov.b64 {%0, h}, %1; }" : "=f"(f) : "l"(v)); return f; }
__device__ __forceinline__ float hi32(u64 v){ float f; asm("{ .reg .f32 l; mov.b64 {l, %0}, %1; }" : "=f"(f) : "l"(v)); return f; }
__device__ __forceinline__ u64 mul2(u64 a, u64 b){ u64 r; asm("mul.rn.f32x2 %0, %1, %2;" : "=l"(r) : "l"(a), "l"(b)); return r; }
__device__ __forceinline__ u64 fma2(u64 a, u64 b, u64 c){ u64 r; asm("fma.rn.f32x2 %0, %1, %2, %3;" : "=l"(r) : "l"(a), "l"(b), "l"(c)); return r; }
__device__ __forceinline__ u64 add2(u64 a, u64 b){ u64 r; asm("add.rn.f32x2 %0, %1, %2;" : "=l"(r) : "l"(a), "l"(b)); return r; }
__device__ __forceinline__ u64 sub2(u64 a, u64 b){ u64 r; asm("sub.rn.f32x2 %0, %1, %2;" : "=l"(r) : "l"(a), "l"(b)); return r; }
__device__ __forceinline__ u64 rxh(u64 C2, u64 S2, u64 T, u64 U){ return fma2(C2, T, mul2(S2, U)); }

// RX on one cross-register wire (packed mask mp) over 16-reg planes
__device__ __forceinline__ void rx_cross(u64* R, u64* I, float c, float s, int mp)
{
    const u64 C2 = bc2(c), S2 = bc2(s), N2 = bc2(-s);
#pragma unroll
    for (int p0 = 0; p0 < 16; ++p0) {
        if (p0 & mp) continue;
        const int p1 = p0 | mp;
        const u64 r0 = R[p0], i0 = I[p0], r1 = R[p1], i1 = I[p1];
        R[p0] = rxh(C2, S2, r0, i1);
        I[p0] = rxh(C2, N2, i0, r1);
        R[p1] = rxh(C2, S2, r1, i0);
        I[p1] = rxh(C2, N2, i1, r0);
    }
}

// RX on the in-register pair-lane wire (scalar lanes)
__device__ __forceinline__ void rx_lane(u64* R, u64* I, float c, float s)
{
#pragma unroll
    for (int p = 0; p < 16; ++p) {
        const float rx = lo32(R[p]), ry = hi32(R[p]);
        const float ix = lo32(I[p]), iy = hi32(I[p]);
        R[p] = pk2(fmaf(c, rx,  s * iy), fmaf(c, ry,  s * ix));
        I[p] = pk2(fmaf(c, ix, -s * ry), fmaf(c, iy, -s * rx));
    }
}

__global__ __launch_bounds__(TPB, 4)
void qnn_kernel(const float* __restrict__ x,
                const float* __restrict__ qw,
                const float* __restrict__ W,
                const float* __restrict__ bias,
                float* __restrict__ out)
{
    __shared__ float cx[NQ], sx[NQ];
    __shared__ float cq[NL * NQ], sq[NL * NQ];
    __shared__ float red[4][NQ];
    __shared__ float zf[NQ];

    float* const bR = dynsm;
    float* const bI = dynsm + PLANE;

    const int tid  = threadIdx.x;
    const int bsmp = blockIdx.x;
    const int lane = tid & 31;
    const int warp = tid >> 5;

    if (tid < NQ) {
        float s, c;
        sincosf(0.5f * x[bsmp * NQ + tid], &s, &c);
        cx[tid] = c; sx[tid] = s;
    }
    if (tid >= 32 && tid < 32 + NL * NQ) {
        const int idx = tid - 32;
        float s, c;
        sincosf(0.5f * qw[idx], &s, &c);
        cq[idx] = c; sq[idx] = s;
    }
    __syncthreads();

    // ---- init (M0): fused AngleEmbedding product state, planar packed ----
    u64 R[16], I[16];
    uint32_t off3p[16];                 // 32 Q3 gather offsets (2x u16)
    const int base = tid << 5;

#pragma unroll
    for (int k = 0; k < 32; ++k) {
        const int i = base | k;
        float mag = 1.0f;
#pragma unroll
        for (int w = 0; w < NQ; ++w)
            mag *= ((i >> (11 - w)) & 1) ? sx[w] : cx[w];
        const int pc = __popc(i) & 3;   // amp = mag * (-i)^popcount
        float re = 0.f, im = 0.f;
        if      (pc == 0) re =  mag;
        else if (pc == 1) im = -mag;
        else if (pc == 2) re = -mag;
        else              im =  mag;

        if (k & 1) { R[k >> 1] = pk2(lo32(R[k >> 1]), re); I[k >> 1] = pk2(lo32(I[k >> 1]), im); }
        else       { R[k >> 1] = pk2(re, 0.f);             I[k >> 1] = pk2(im, 0.f); }

        // sigma(i): CNOT-ring gather source amp j (new[i] = old[j])
        int j = i;
#pragma unroll
        for (int w = NQ - 1; w >= 0; --w) {
            const int t  = (w + 1) % NQ;
            const int bc = (j >> (11 - w)) & 1;
            j ^= bc << (11 - t);
        }
        // address of j under layout M2
        const uint32_t row = (uint32_t)((((j >> 8) & 3) << 5) | (j & 31));
        const uint32_t col = (uint32_t)(((j >> 10) << 3) | ((j >> 5) & 7));
        const uint32_t off = row * ST + col;
        if (k & 1) off3p[k >> 1] |= off << 16;
        else       off3p[k >> 1]  = off;
    }

    const int st    = tid * ST;                                     // own-row store base
    const int base1 = ((tid >> 5) << 5) * ST + (tid & 31);          // T1: + 33*k'
    const int base2 = (tid & 31) * ST + ((tid >> 5) << 3);          // T2: + k''>>3 * 33*32 + (k''&7)

    // ---- 6 entangler layers ----
#pragma unroll 1
    for (int l = 0; l < NL; ++l) {
        const float* cl = &cq[l * NQ];
        const float* sl = &sq[l * NQ];

        // RX wires 7-10 (cross) + 11 (lane)   [M0]
        rx_cross(R, I, cl[7], sl[7], 8);
        rx_cross(R, I, cl[8], sl[8], 4);
        rx_cross(R, I, cl[9], sl[9], 2);
        rx_cross(R, I, cl[10], sl[10], 1);
        rx_lane (R, I, cl[11], sl[11]);

        // T1: M0 -> M1
        __syncthreads();
#pragma unroll
        for (int p = 0; p < 16; ++p) {
            bR[st + 2*p] = lo32(R[p]); bR[st + 2*p + 1] = hi32(R[p]);
            bI[st + 2*p] = lo32(I[p]); bI[st + 2*p + 1] = hi32(I[p]);
        }
        __syncthreads();
#pragma unroll
        for (int q = 0; q < 16; ++q) {
            const int a0 = base1 + (2*q) * ST, a1 = a0 + ST;
            R[q] = pk2(bR[a0], bR[a1]);
            I[q] = pk2(bI[a0], bI[a1]);
        }

        // RX wires 2-5 (cross) + 6 (lane)     [M1]
        rx_cross(R, I, cl[2], sl[2], 8);
        rx_cross(R, I, cl[3], sl[3], 4);
        rx_cross(R, I, cl[4], sl[4], 2);
        rx_cross(R, I, cl[5], sl[5], 1);
        rx_lane (R, I, cl[6], sl[6]);

        // T2: M1 -> M2
        __syncthreads();
#pragma unroll
        for (int p = 0; p < 16; ++p) {
            bR[st + 2*p] = lo32(R[p]); bR[st + 2*p + 1] = hi32(R[p]);
            bI[st + 2*p] = lo32(I[p]); bI[st + 2*p + 1] = hi32(I[p]);
        }
        __syncthreads();
#pragma unroll
        for (int q = 0; q < 16; ++q) {
            const int k0 = 2*q;
            const int a0 = base2 + (k0 >> 3) * (ST * 32) + (k0 & 7);
            R[q] = pk2(bR[a0], bR[a0 + 1]);     // k''=2q,2q+1 are address-consecutive
            I[q] = pk2(bI[a0], bI[a0 + 1]);
        }

        // RX wires 0,1 (cross)                 [M2]
        rx_cross(R, I, cl[0], sl[0], 8);
        rx_cross(R, I, cl[1], sl[1], 4);

        // T3: fused CNOT-ring permutation, M2 -> M0
        __syncthreads();
#pragma unroll
        for (int p = 0; p < 16; ++p) {
            bR[st + 2*p] = lo32(R[p]); bR[st + 2*p + 1] = hi32(R[p]);
            bI[st + 2*p] = lo32(I[p]); bI[st + 2*p + 1] = hi32(I[p]);
        }
        __syncthreads();
#pragma unroll
        for (int q = 0; q < 16; ++q) {
            const int o0 = off3p[q] & 0xFFFF;
            const int o1 = off3p[q] >> 16;
            R[q] = pk2(bR[o0], bR[o1]);
            I[q] = pk2(bI[o0], bI[o1]);
        }
    }

    // ---- <Z_w> readout (M0) ----
    u64 pt2 = 0ull, z7 = 0ull, z8 = 0ull, z9 = 0ull, z10 = 0ull;
    float z11 = 0.f;
#pragma unroll
    for (int p = 0; p < 16; ++p) {
        const u64 P = fma2(R[p], R[p], mul2(I[p], I[p]));
        pt2 = add2(pt2, P);
        z7  = (p & 8) ? sub2(z7,  P) : add2(z7,  P);
        z8  = (p & 4) ? sub2(z8,  P) : add2(z8,  P);
        z9  = (p & 2) ? sub2(z9,  P) : add2(z9,  P);
        z10 = (p & 1) ? sub2(z10, P) : add2(z10, P);
        z11 += lo32(P) - hi32(P);
    }
    const float ptot = lo32(pt2) + hi32(pt2);

    float z12[NQ];
#pragma unroll
    for (int w = 0; w < 7; ++w)                  // wires 0..6 <- tid bits 6..0
        z12[w] = ((tid >> (6 - w)) & 1) ? -ptot : ptot;
    z12[7]  = lo32(z7)  + hi32(z7);
    z12[8]  = lo32(z8)  + hi32(z8);
    z12[9]  = lo32(z9)  + hi32(z9);
    z12[10] = lo32(z10) + hi32(z10);
    z12[11] = z11;

#pragma unroll
    for (int w = 0; w < NQ; ++w) {
#pragma unroll
        for (int o = 16; o > 0; o >>= 1)
            z12[w] += __shfl_xor_sync(0xffffffffu, z12[w], o);
    }
    if (lane == 0) {
#pragma unroll
        for (int w = 0; w < NQ; ++w) red[warp][w] = z12[w];
    }
    __syncthreads();
    if (tid < NQ)
        zf[tid] = red[0][tid] + red[1][tid] + red[2][tid] + red[3][tid];
    __syncthreads();

    // ---- classifier head ----
    if (tid < NC) {
        float acc = bias[tid];
#pragma unroll
        for (int w = 0; w < NQ; ++w)
            acc = fmaf(zf[w], W[tid * NQ + w], acc);
        out[bsmp * NC + tid] = acc;
    }
}

extern "C" void kernel_launch(void* const* d_in, const int* in_sizes, int n_in,
                              void* d_out, int out_size)
{
    const float* x  = (const float*)d_in[0];   // (512, 12)
    const float* qw = (const float*)d_in[1];   // (6, 12)
    const float* W  = (const float*)d_in[2];   // (64, 12)
    const float* bs = (const float*)d_in[3];   // (64,)
    float* out = (float*)d_out;                // (512, 64)

    const int smem = SMEMF * (int)sizeof(float);   // 33792 B
    cudaFuncSetAttribute(qnn_kernel, cudaFuncAttributeMaxDynamicSharedMemorySize, smem);
    qnn_kernel<<<512, TPB, smem>>>(x, qw, W, bs, out);
}